// round 2
// baseline (speedup 1.0000x reference)
#include <cuda_runtime.h>
#include <math.h>

#define NFEAT 128
#define HID   64
#define NCLS  40
#define MAXN  100000
#define MAXE  600000

// ---------------- scratch (static __device__ per harness rules) ----------------
__device__ float g_t1[(size_t)MAXN * 128];  // [x@W1l | x@W1r]  51.2 MB
__device__ float g_h [(size_t)MAXN * 64];   // hidden           25.6 MB
__device__ float g_t2[(size_t)MAXN * 80];   // [h@W2l | h@W2r]  32 MB
__device__ int   g_deg[MAXN];
__device__ int   g_cur[MAXN];
__device__ int   g_rowptr[MAXN + 1];
__device__ int   g_adj[MAXE];
__device__ int   g_is64;   // 1 if edge_index is int64, 0 if int32

// ---------------- f32x2 packed math (sm_103a) ----------------
#define PACK2(d, lo, hi) asm("mov.b64 %0, {%1,%2};" : "=l"(d) : "f"(lo), "f"(hi))
#define UNPACK2(lo, hi, s) asm("mov.b64 {%0,%1}, %2;" : "=f"(lo), "=f"(hi) : "l"(s))
#define FMA2(d, a, b, c) asm("fma.rn.f32x2 %0, %1, %2, %3;" : "=l"(d) : "l"(a), "l"(b), "l"(c))

// ---------------- dtype detect ----------------
// If the buffer holds int32 indices, interpreting as int64 combines two random
// indices: value = lo | (hi << 32). With 512 samples of random hi in
// [0,100000), P(all hi == 0) ~ 0 -> reliably flags int32.
__global__ void k_detect(const void* __restrict__ ei, int E, int N) {
    __shared__ int bad;
    if (threadIdx.x == 0) bad = 0;
    __syncthreads();
    const long long* p = (const long long*)ei;
    int samples = (E < 512) ? E : 512;
    for (int i = threadIdx.x; i < samples; i += blockDim.x) {
        long long v = p[i];
        if (v < 0 || v >= (long long)N) atomicExch(&bad, 1);
    }
    __syncthreads();
    if (threadIdx.x == 0) g_is64 = bad ? 0 : 1;
}

__device__ __forceinline__ int load_idx(const void* ei, int pos) {
    if (g_is64) {
        long long v = ((const long long*)ei)[pos];
        return (int)v;
    } else {
        return ((const int*)ei)[pos];
    }
}

// ---------------- graph build ----------------
__global__ void k_zero(int n) {
    int i = blockIdx.x * blockDim.x + threadIdx.x;
    if (i < n) { g_deg[i] = 0; g_cur[i] = 0; }
}

__global__ void k_hist(const void* __restrict__ ei, int E, int N) {
    int e = blockIdx.x * blockDim.x + threadIdx.x;
    if (e < E) {
        int dst = load_idx(ei, E + e);
        dst = min(max(dst, 0), N - 1);
        atomicAdd(&g_deg[dst], 1);
    }
}

// single-block exclusive scan -> g_rowptr (shuffle-based, 4 elems/thread/chunk)
__global__ void k_scan(int n) {
    const int tid  = threadIdx.x;          // 1024 threads
    const int lane = tid & 31, wid = tid >> 5;
    __shared__ int wsum[32];
    __shared__ int s_off;
    if (tid == 0) { s_off = 0; g_rowptr[0] = 0; }
    __syncthreads();
    for (int base = 0; base < n; base += 4096) {
        int idx = base + tid * 4;
        int v0 = (idx + 0 < n) ? g_deg[idx + 0] : 0;
        int v1 = (idx + 1 < n) ? g_deg[idx + 1] : 0;
        int v2 = (idx + 2 < n) ? g_deg[idx + 2] : 0;
        int v3 = (idx + 3 < n) ? g_deg[idx + 3] : 0;
        int s = v0 + v1 + v2 + v3;
        int sc = s;
        #pragma unroll
        for (int d = 1; d < 32; d <<= 1) {
            int t = __shfl_up_sync(0xffffffffu, sc, d);
            if (lane >= d) sc += t;
        }
        if (lane == 31) wsum[wid] = sc;
        __syncthreads();
        if (wid == 0) {
            int ws = wsum[lane];
            #pragma unroll
            for (int d = 1; d < 32; d <<= 1) {
                int t = __shfl_up_sync(0xffffffffu, ws, d);
                if (lane >= d) ws += t;
            }
            wsum[lane] = ws;
        }
        __syncthreads();
        int warp_excl = (wid == 0) ? 0 : wsum[wid - 1];
        int excl = s_off + warp_excl + (sc - s);
        int p0 = excl + v0, p1 = p0 + v1, p2 = p1 + v2, p3 = p2 + v3;
        if (idx + 0 < n) g_rowptr[idx + 1] = p0;
        if (idx + 1 < n) g_rowptr[idx + 2] = p1;
        if (idx + 2 < n) g_rowptr[idx + 3] = p2;
        if (idx + 3 < n) g_rowptr[idx + 4] = p3;
        __syncthreads();
        if (tid == 1023) s_off += warp_excl + sc;   // chunk total
        __syncthreads();
    }
}

__global__ void k_fill(const void* __restrict__ ei, int E, int N) {
    int e = blockIdx.x * blockDim.x + threadIdx.x;
    if (e < E) {
        int dst = load_idx(ei, E + e);
        int src = load_idx(ei, e);
        dst = min(max(dst, 0), N - 1);
        src = min(max(src, 0), N - 1);
        int pos = g_rowptr[dst] + atomicAdd(&g_cur[dst], 1);
        if (pos < E) g_adj[pos] = src;
    }
}

// ---------------- dual GEMM: T[n, 2*OUTH] = X[n,IN] @ [Wl | Wr] ----------------
// 64-row tile, 8x4 per-thread register tile, f32x2 row-pair accumulators.
template <int IN, int OUTH, int TM>
__global__ void __launch_bounds__(8 * (2 * OUTH / 4))
k_gemm_dual(const float* __restrict__ X, const float* __restrict__ Wl,
            const float* __restrict__ Wr, float* __restrict__ T, int n) {
    constexpr int OUT = 2 * OUTH;
    constexpr int CQ  = OUT / 4;        // col quads
    constexpr int NT  = 8 * CQ;         // threads
    extern __shared__ float sm[];
    float* Ws = sm;                     // [IN][OUT]
    float* Xs = sm + IN * OUT;          // [TM][IN]
    const int tid = threadIdx.x;

    for (int i = tid; i < IN * OUTH; i += NT) {
        int k = i / OUTH, c = i % OUTH;
        Ws[k * OUT + c]        = Wl[i];
        Ws[k * OUT + OUTH + c] = Wr[i];
    }
    const int row0 = blockIdx.x * TM;
    for (int i = tid; i < TM * (IN / 4); i += NT) {
        int r = i / (IN / 4), kq = i % (IN / 4);
        float4 v = make_float4(0.f, 0.f, 0.f, 0.f);
        if (row0 + r < n) v = *(const float4*)(X + (size_t)(row0 + r) * IN + kq * 4);
        *(float4*)(Xs + r * IN + kq * 4) = v;
    }
    __syncthreads();

    const int tx = tid % CQ;            // col quad
    const int ty = tid / CQ;            // row group of 8
    const float* xrow = Xs + ty * 8 * IN;
    const float* wcol = Ws + tx * 4;

    unsigned long long acc[4][4];
    #pragma unroll
    for (int a = 0; a < 4; a++)
        #pragma unroll
        for (int b = 0; b < 4; b++) acc[a][b] = 0ull;

    #pragma unroll 4
    for (int k = 0; k < IN; k++) {
        float a0 = xrow[k],          a1 = xrow[IN + k];
        float a2 = xrow[2 * IN + k], a3 = xrow[3 * IN + k];
        float a4 = xrow[4 * IN + k], a5 = xrow[5 * IN + k];
        float a6 = xrow[6 * IN + k], a7 = xrow[7 * IN + k];
        float4 w = *(const float4*)(wcol + k * OUT);
        unsigned long long ap[4], wd[4];
        PACK2(ap[0], a0, a1); PACK2(ap[1], a2, a3);
        PACK2(ap[2], a4, a5); PACK2(ap[3], a6, a7);
        PACK2(wd[0], w.x, w.x); PACK2(wd[1], w.y, w.y);
        PACK2(wd[2], w.z, w.z); PACK2(wd[3], w.w, w.w);
        #pragma unroll
        for (int rp = 0; rp < 4; rp++)
            #pragma unroll
            for (int c = 0; c < 4; c++)
                FMA2(acc[rp][c], ap[rp], wd[c], acc[rp][c]);
    }

    #pragma unroll
    for (int rp = 0; rp < 4; rp++) {
        int r = row0 + ty * 8 + rp * 2;
        float lo[4], hi[4];
        #pragma unroll
        for (int c = 0; c < 4; c++) UNPACK2(lo[c], hi[c], acc[rp][c]);
        if (r < n)
            *(float4*)(T + (size_t)r * OUT + tx * 4) = make_float4(lo[0], lo[1], lo[2], lo[3]);
        if (r + 1 < n)
            *(float4*)(T + (size_t)(r + 1) * OUT + tx * 4) = make_float4(hi[0], hi[1], hi[2], hi[3]);
    }
}

// ---------------- aggregate (CSR gather) + mean + residual + bias (+sigmoid) ----
template <int ROWLEN, int OUTC, bool SIG>
__global__ void k_finish(const float* __restrict__ T, const float* __restrict__ bias,
                         float* __restrict__ out, int n) {
    constexpr int Q = OUTC / 4;
    int gid = blockIdx.x * blockDim.x + threadIdx.x;
    int node = gid / Q;
    int q = gid - node * Q;
    if (node >= n) return;
    int s = g_rowptr[node], e = g_rowptr[node + 1];
    float4 acc = make_float4(0.f, 0.f, 0.f, 0.f);
    for (int p = s; p < e; p++) {
        int j = g_adj[p];
        float4 v = *(const float4*)(T + (size_t)j * ROWLEN + q * 4);
        acc.x += v.x; acc.y += v.y; acc.z += v.z; acc.w += v.w;
    }
    float inv = 1.f / fmaxf((float)(e - s), 1.f);
    float4 r = *(const float4*)(T + (size_t)node * ROWLEN + OUTC + q * 4);
    float4 b = *(const float4*)(bias + q * 4);
    float4 o;
    o.x = fmaf(acc.x, inv, r.x + b.x);
    o.y = fmaf(acc.y, inv, r.y + b.y);
    o.z = fmaf(acc.z, inv, r.z + b.z);
    o.w = fmaf(acc.w, inv, r.w + b.w);
    if (SIG) {
        o.x = 1.f / (1.f + expf(-o.x));
        o.y = 1.f / (1.f + expf(-o.y));
        o.z = 1.f / (1.f + expf(-o.z));
        o.w = 1.f / (1.f + expf(-o.w));
    }
    *(float4*)(out + (size_t)node * OUTC + q * 4) = o;
}

// ---------------- launch ----------------
extern "C" void kernel_launch(void* const* d_in, const int* in_sizes, int n_in,
                              void* d_out, int out_size) {
    const float* x   = (const float*)d_in[0];
    const void*  ei  = d_in[1];
    const float* W1l = (const float*)d_in[2];
    const float* b1  = (const float*)d_in[3];
    const float* W1r = (const float*)d_in[4];
    const float* W2l = (const float*)d_in[5];
    const float* b2  = (const float*)d_in[6];
    const float* W2r = (const float*)d_in[7];
    float* out = (float*)d_out;

    const int N = in_sizes[0] / NFEAT;
    const int E = in_sizes[1] / 2;

    void *t1p, *hp, *t2p;
    cudaGetSymbolAddress(&t1p, g_t1);
    cudaGetSymbolAddress(&hp,  g_h);
    cudaGetSymbolAddress(&t2p, g_t2);

    constexpr int SMEM1 = (128 * 128 + 64 * 128) * 4;  // 98,304 B
    constexpr int SMEM2 = (64 * 80 + 64 * 64) * 4;     // 36,864 B
    cudaFuncSetAttribute(k_gemm_dual<128, 64, 64>,
                         cudaFuncAttributeMaxDynamicSharedMemorySize, SMEM1);
    cudaFuncSetAttribute(k_gemm_dual<64, 40, 64>,
                         cudaFuncAttributeMaxDynamicSharedMemorySize, SMEM2);

    // dtype probe + graph build (shared by both layers)
    k_detect<<<1, 256>>>(ei, E, N);
    k_zero<<<(N + 255) / 256, 256>>>(N);
    k_hist<<<(E + 255) / 256, 256>>>(ei, E, N);
    k_scan<<<1, 1024>>>(N);
    k_fill<<<(E + 255) / 256, 256>>>(ei, E, N);

    // layer 1
    k_gemm_dual<128, 64, 64><<<(N + 63) / 64, 256, SMEM1>>>(x, W1l, W1r, (float*)t1p, N);
    int tot1 = N * (HID / 4);
    k_finish<128, 64, true><<<(tot1 + 255) / 256, 256>>>((const float*)t1p, b1, (float*)hp, N);

    // layer 2
    k_gemm_dual<64, 40, 64><<<(N + 63) / 64, 160, SMEM2>>>((const float*)hp, W2l, W2r, (float*)t2p, N);
    int tot2 = N * (NCLS / 4);
    k_finish<80, 40, false><<<(tot2 + 255) / 256, 256>>>((const float*)t2p, b2, out, N);
}

// round 3
// speedup vs baseline: 1.1516x; 1.1516x over previous
#include <cuda_runtime.h>
#include <math.h>

#define NFEAT 128
#define HID   64
#define NCLS  40
#define MAXN  100000
#define MAXE  600000
#define SCAN_CHUNK 4096
#define MAXB ((MAXN + SCAN_CHUNK - 1) / SCAN_CHUNK)   // 25

// ---------------- scratch ----------------
__device__ float g_t1[(size_t)MAXN * 128];
__device__ float g_h [(size_t)MAXN * 64];
__device__ float g_t2[(size_t)MAXN * 80];
__device__ int   g_deg[MAXN];
__device__ int   g_cur[MAXN];
__device__ int   g_rowptr[MAXN + 1];
__device__ int   g_adj[MAXE];
__device__ int   g_bsum[32];
__device__ int   g_boff[32];
__device__ int   g_is64;

// ---------------- f32x2 packed math (sm_103a) ----------------
#define PACK2(d, lo, hi) asm("mov.b64 %0, {%1,%2};" : "=l"(d) : "f"(lo), "f"(hi))
#define UNPACK2(lo, hi, s) asm("mov.b64 {%0,%1}, %2;" : "=f"(lo), "=f"(hi) : "l"(s))
#define FMA2(d, a, b, c) asm("fma.rn.f32x2 %0, %1, %2, %3;" : "=l"(d) : "l"(a), "l"(b), "l"(c))

// ---------------- dtype detect ----------------
__global__ void k_detect(const void* __restrict__ ei, int E, int N) {
    __shared__ int bad;
    if (threadIdx.x == 0) bad = 0;
    __syncthreads();
    const long long* p = (const long long*)ei;
    int samples = (E < 512) ? E : 512;
    for (int i = threadIdx.x; i < samples; i += blockDim.x) {
        long long v = p[i];
        if (v < 0 || v >= (long long)N) atomicExch(&bad, 1);
    }
    __syncthreads();
    if (threadIdx.x == 0) g_is64 = bad ? 0 : 1;
}

__device__ __forceinline__ int load_idx(const void* ei, int pos) {
    if (g_is64) return (int)((const long long*)ei)[pos];
    return ((const int*)ei)[pos];
}

// ---------------- graph build ----------------
__global__ void k_zero(int n) {
    int i = blockIdx.x * blockDim.x + threadIdx.x;
    if (i < n) { g_deg[i] = 0; g_cur[i] = 0; }
}

__global__ void k_hist(const void* __restrict__ ei, int E, int N) {
    int e = blockIdx.x * blockDim.x + threadIdx.x;
    if (e < E) {
        int dst = load_idx(ei, E + e);
        dst = min(max(dst, 0), N - 1);
        atomicAdd(&g_deg[dst], 1);
    }
}

// ---- phase 1: per-block local scan (4096 elems / block, 4 / thread) ----
__global__ void k_scan_part(int n) {
    const int tid = threadIdx.x, lane = tid & 31, wid = tid >> 5;
    __shared__ int wsum[32];
    int idx = blockIdx.x * SCAN_CHUNK + tid * 4;
    int v0 = (idx + 0 < n) ? g_deg[idx + 0] : 0;
    int v1 = (idx + 1 < n) ? g_deg[idx + 1] : 0;
    int v2 = (idx + 2 < n) ? g_deg[idx + 2] : 0;
    int v3 = (idx + 3 < n) ? g_deg[idx + 3] : 0;
    int s = v0 + v1 + v2 + v3;
    int sc = s;
    #pragma unroll
    for (int d = 1; d < 32; d <<= 1) {
        int t = __shfl_up_sync(0xffffffffu, sc, d);
        if (lane >= d) sc += t;
    }
    if (lane == 31) wsum[wid] = sc;
    __syncthreads();
    if (wid == 0) {
        int ws = wsum[lane];
        #pragma unroll
        for (int d = 1; d < 32; d <<= 1) {
            int t = __shfl_up_sync(0xffffffffu, ws, d);
            if (lane >= d) ws += t;
        }
        wsum[lane] = ws;
    }
    __syncthreads();
    int warp_excl = (wid == 0) ? 0 : wsum[wid - 1];
    int excl = warp_excl + (sc - s);        // block-local exclusive prefix
    int p0 = excl + v0, p1 = p0 + v1, p2 = p1 + v2, p3 = p2 + v3;
    if (idx + 0 < n) g_rowptr[idx + 1] = p0;
    if (idx + 1 < n) g_rowptr[idx + 2] = p1;
    if (idx + 2 < n) g_rowptr[idx + 3] = p2;
    if (idx + 3 < n) g_rowptr[idx + 4] = p3;
    if (tid == 1023) g_bsum[blockIdx.x] = warp_excl + sc;   // block total
}

// ---- phase 2: exclusive scan of block sums (nb <= 32) ----
__global__ void k_scan_top(int nb) {
    int lane = threadIdx.x;
    int v = (lane < nb) ? g_bsum[lane] : 0;
    int sc = v;
    #pragma unroll
    for (int d = 1; d < 32; d <<= 1) {
        int t = __shfl_up_sync(0xffffffffu, sc, d);
        if (lane >= d) sc += t;
    }
    if (lane < nb) g_boff[lane] = sc - v;
}

// ---- phase 3: add block offsets ----
__global__ void k_scan_add(int n) {
    int off = g_boff[blockIdx.x];
    int idx = blockIdx.x * SCAN_CHUNK + threadIdx.x * 4;
    if (blockIdx.x == 0 && threadIdx.x == 0) g_rowptr[0] = 0;
    if (blockIdx.x > 0) {
        #pragma unroll
        for (int i = 0; i < 4; i++)
            if (idx + i < n) g_rowptr[idx + i + 1] += off;
    }
}

__global__ void k_fill(const void* __restrict__ ei, int E, int N) {
    int e = blockIdx.x * blockDim.x + threadIdx.x;
    if (e < E) {
        int dst = load_idx(ei, E + e);
        int src = load_idx(ei, e);
        dst = min(max(dst, 0), N - 1);
        src = min(max(src, 0), N - 1);
        int pos = g_rowptr[dst] + atomicAdd(&g_cur[dst], 1);
        if (pos < E) g_adj[pos] = src;
    }
}

// ---------------- dual GEMM: T[n, 2*OUTH] = X[n,IN] @ [Wl | Wr] ----------------
template <int IN, int OUTH, int TM>
__global__ void __launch_bounds__(8 * (2 * OUTH / 4))
k_gemm_dual(const float* __restrict__ X, const float* __restrict__ Wl,
            const float* __restrict__ Wr, float* __restrict__ T, int n) {
    constexpr int OUT = 2 * OUTH;
    constexpr int CQ  = OUT / 4;
    constexpr int NT  = 8 * CQ;
    extern __shared__ float sm[];
    float* Ws = sm;                     // [IN][OUT]
    float* Xs = sm + IN * OUT;          // [TM][IN]
    const int tid = threadIdx.x;

    for (int i = tid; i < IN * OUTH; i += NT) {
        int k = i / OUTH, c = i % OUTH;
        Ws[k * OUT + c]        = Wl[i];
        Ws[k * OUT + OUTH + c] = Wr[i];
    }
    const int row0 = blockIdx.x * TM;
    for (int i = tid; i < TM * (IN / 4); i += NT) {
        int r = i / (IN / 4), kq = i % (IN / 4);
        float4 v = make_float4(0.f, 0.f, 0.f, 0.f);
        if (row0 + r < n) v = *(const float4*)(X + (size_t)(row0 + r) * IN + kq * 4);
        *(float4*)(Xs + r * IN + kq * 4) = v;
    }
    __syncthreads();

    const int tx = tid % CQ;
    const int ty = tid / CQ;
    const float* xrow = Xs + ty * 8 * IN;
    const float* wcol = Ws + tx * 4;

    unsigned long long acc[4][4];
    #pragma unroll
    for (int a = 0; a < 4; a++)
        #pragma unroll
        for (int b = 0; b < 4; b++) acc[a][b] = 0ull;

    for (int k = 0; k < IN; k += 4) {
        float4 xv[8];
        #pragma unroll
        for (int r = 0; r < 8; r++)
            xv[r] = *(const float4*)(xrow + r * IN + k);
        float4 wq[4];
        #pragma unroll
        for (int i = 0; i < 4; i++)
            wq[i] = *(const float4*)(wcol + (k + i) * OUT);
        #pragma unroll
        for (int i = 0; i < 4; i++) {
            unsigned long long ap[4], wd[4];
            PACK2(ap[0], (&xv[0].x)[i], (&xv[1].x)[i]);
            PACK2(ap[1], (&xv[2].x)[i], (&xv[3].x)[i]);
            PACK2(ap[2], (&xv[4].x)[i], (&xv[5].x)[i]);
            PACK2(ap[3], (&xv[6].x)[i], (&xv[7].x)[i]);
            PACK2(wd[0], wq[i].x, wq[i].x);
            PACK2(wd[1], wq[i].y, wq[i].y);
            PACK2(wd[2], wq[i].z, wq[i].z);
            PACK2(wd[3], wq[i].w, wq[i].w);
            #pragma unroll
            for (int rp = 0; rp < 4; rp++)
                #pragma unroll
                for (int c = 0; c < 4; c++)
                    FMA2(acc[rp][c], ap[rp], wd[c], acc[rp][c]);
        }
    }

    #pragma unroll
    for (int rp = 0; rp < 4; rp++) {
        int r = row0 + ty * 8 + rp * 2;
        float lo[4], hi[4];
        #pragma unroll
        for (int c = 0; c < 4; c++) UNPACK2(lo[c], hi[c], acc[rp][c]);
        if (r < n)
            *(float4*)(T + (size_t)r * OUT + tx * 4) = make_float4(lo[0], lo[1], lo[2], lo[3]);
        if (r + 1 < n)
            *(float4*)(T + (size_t)(r + 1) * OUT + tx * 4) = make_float4(hi[0], hi[1], hi[2], hi[3]);
    }
}

// ---------------- aggregate + mean + residual + bias (+sigmoid) ----------------
template <int ROWLEN, int OUTC, bool SIG>
__global__ void k_finish(const float* __restrict__ T, const float* __restrict__ bias,
                         float* __restrict__ out, int n) {
    constexpr int Q = OUTC / 4;
    int gid = blockIdx.x * blockDim.x + threadIdx.x;
    int node = gid / Q;
    int q = gid - node * Q;
    if (node >= n) return;
    int s = g_rowptr[node], e = g_rowptr[node + 1];
    float4 acc = make_float4(0.f, 0.f, 0.f, 0.f);
    for (int p = s; p < e; p++) {
        int j = g_adj[p];
        float4 v = *(const float4*)(T + (size_t)j * ROWLEN + q * 4);
        acc.x += v.x; acc.y += v.y; acc.z += v.z; acc.w += v.w;
    }
    float inv = 1.f / fmaxf((float)(e - s), 1.f);
    float4 r = *(const float4*)(T + (size_t)node * ROWLEN + OUTC + q * 4);
    float4 b = *(const float4*)(bias + q * 4);
    float4 o;
    o.x = fmaf(acc.x, inv, r.x + b.x);
    o.y = fmaf(acc.y, inv, r.y + b.y);
    o.z = fmaf(acc.z, inv, r.z + b.z);
    o.w = fmaf(acc.w, inv, r.w + b.w);
    if (SIG) {
        o.x = 1.f / (1.f + expf(-o.x));
        o.y = 1.f / (1.f + expf(-o.y));
        o.z = 1.f / (1.f + expf(-o.z));
        o.w = 1.f / (1.f + expf(-o.w));
    }
    *(float4*)(out + (size_t)node * OUTC + q * 4) = o;
}

// ---------------- launch ----------------
extern "C" void kernel_launch(void* const* d_in, const int* in_sizes, int n_in,
                              void* d_out, int out_size) {
    const float* x   = (const float*)d_in[0];
    const void*  ei  = d_in[1];
    const float* W1l = (const float*)d_in[2];
    const float* b1  = (const float*)d_in[3];
    const float* W1r = (const float*)d_in[4];
    const float* W2l = (const float*)d_in[5];
    const float* b2  = (const float*)d_in[6];
    const float* W2r = (const float*)d_in[7];
    float* out = (float*)d_out;

    const int N = in_sizes[0] / NFEAT;
    const int E = in_sizes[1] / 2;
    const int NB = (N + SCAN_CHUNK - 1) / SCAN_CHUNK;

    void *t1p, *hp, *t2p;
    cudaGetSymbolAddress(&t1p, g_t1);
    cudaGetSymbolAddress(&hp,  g_h);
    cudaGetSymbolAddress(&t2p, g_t2);

    constexpr int SMEM1 = (128 * 128 + 64 * 128) * 4;  // 98,304 B
    constexpr int SMEM2 = (64 * 80 + 64 * 64) * 4;     // 36,864 B
    cudaFuncSetAttribute(k_gemm_dual<128, 64, 64>,
                         cudaFuncAttributeMaxDynamicSharedMemorySize, SMEM1);
    cudaFuncSetAttribute(k_gemm_dual<64, 40, 64>,
                         cudaFuncAttributeMaxDynamicSharedMemorySize, SMEM2);

    // dtype probe + graph build
    k_detect<<<1, 256>>>(ei, E, N);
    k_zero<<<(N + 255) / 256, 256>>>(N);
    k_hist<<<(E + 255) / 256, 256>>>(ei, E, N);
    k_scan_part<<<NB, 1024>>>(N);
    k_scan_top<<<1, 32>>>(NB);
    k_scan_add<<<NB, 1024>>>(N);
    k_fill<<<(E + 255) / 256, 256>>>(ei, E, N);

    // layer 1
    k_gemm_dual<128, 64, 64><<<(N + 63) / 64, 256, SMEM1>>>(x, W1l, W1r, (float*)t1p, N);
    int tot1 = N * (HID / 4);
    k_finish<128, 64, true><<<(tot1 + 255) / 256, 256>>>((const float*)t1p, b1, (float*)hp, N);

    // layer 2
    k_gemm_dual<64, 40, 64><<<(N + 63) / 64, 160, SMEM2>>>((const float*)hp, W2l, W2r, (float*)t2p, N);
    int tot2 = N * (NCLS / 4);
    k_finish<80, 40, false><<<(tot2 + 255) / 256, 256>>>((const float*)t2p, b2, out, N);
}